// round 15
// baseline (speedup 1.0000x reference)
#include <cuda_runtime.h>
#include <cuda_bf16.h>
#include <cuda_fp16.h>
#include <cstdint>

#define S_LEN   2048
#define DMODEL  2048
#define NHEADS  16
#define DHEAD   128
#define BATCH   2
#define MTOT    (BATCH * S_LEN)
#define QKVDIM  (3 * DMODEL)

// Scratch: GEMM operands fp16 (A split hi/lo, B hi only); attention qkv bf16 hi/lo.
__device__ __half g_xh[MTOT * DMODEL],  g_xl[MTOT * DMODEL];
__device__ __half g_wqh[DMODEL * QKVDIM];
__device__ __half g_woh[DMODEL * DMODEL];
__device__ __nv_bfloat16 g_qkvh[MTOT * QKVDIM], g_qkvl[MTOT * QKVDIM];
__device__ __half g_atth[MTOT * DMODEL], g_attl[MTOT * DMODEL];

// ---------------------------------------------------------------------------
// Helpers
// ---------------------------------------------------------------------------
__device__ __forceinline__ void split2(float a, float b, uint32_t& hi, uint32_t& lo) {
    __nv_bfloat162 h = __floats2bfloat162_rn(a, b);
    float la = a - __bfloat162float(h.x);
    float lb = b - __bfloat162float(h.y);
    __nv_bfloat162 l = __floats2bfloat162_rn(la, lb);
    hi = *reinterpret_cast<uint32_t*>(&h);
    lo = *reinterpret_cast<uint32_t*>(&l);
}
__device__ __forceinline__ void split2h(float a, float b, uint32_t& hi, uint32_t& lo) {
    __half2 h = __floats2half2_rn(a, b);
    float la = a - __low2float(h);
    float lb = b - __high2float(h);
    __half2 l = __floats2half2_rn(la, lb);
    hi = *reinterpret_cast<uint32_t*>(&h);
    lo = *reinterpret_cast<uint32_t*>(&l);
}
__device__ __forceinline__ float ex2f(float x) {
    float y;
    asm("ex2.approx.f32 %0, %1;" : "=f"(y) : "f"(x));
    return y;
}
__device__ __forceinline__ void ldm_x4(uint32_t* r, const void* p) {
    uint32_t a = (uint32_t)__cvta_generic_to_shared(p);
    asm volatile("ldmatrix.sync.aligned.m8n8.x4.shared.b16 {%0,%1,%2,%3}, [%4];"
                 : "=r"(r[0]), "=r"(r[1]), "=r"(r[2]), "=r"(r[3]) : "r"(a));
}
__device__ __forceinline__ void ldm_x4_t(uint32_t* r, const void* p) {
    uint32_t a = (uint32_t)__cvta_generic_to_shared(p);
    asm volatile("ldmatrix.sync.aligned.m8n8.x4.trans.shared.b16 {%0,%1,%2,%3}, [%4];"
                 : "=r"(r[0]), "=r"(r[1]), "=r"(r[2]), "=r"(r[3]) : "r"(a));
}
__device__ __forceinline__ void mma_bf16(float* c, const uint32_t* a, uint32_t b0, uint32_t b1) {
    asm volatile(
        "mma.sync.aligned.m16n8k16.row.col.f32.bf16.bf16.f32 "
        "{%0,%1,%2,%3}, {%4,%5,%6,%7}, {%8,%9}, {%0,%1,%2,%3};"
        : "+f"(c[0]), "+f"(c[1]), "+f"(c[2]), "+f"(c[3])
        : "r"(a[0]), "r"(a[1]), "r"(a[2]), "r"(a[3]), "r"(b0), "r"(b1));
}
__device__ __forceinline__ void mma_f16(float* c, const uint32_t* a, uint32_t b0, uint32_t b1) {
    asm volatile(
        "mma.sync.aligned.m16n8k16.row.col.f32.f16.f16.f32 "
        "{%0,%1,%2,%3}, {%4,%5,%6,%7}, {%8,%9}, {%0,%1,%2,%3};"
        : "+f"(c[0]), "+f"(c[1]), "+f"(c[2]), "+f"(c[3])
        : "r"(a[0]), "r"(a[1]), "r"(a[2]), "r"(a[3]), "r"(b0), "r"(b1));
}
__device__ __forceinline__ void cpasync16(void* smem_dst, const void* g) {
    uint32_t a = (uint32_t)__cvta_generic_to_shared(smem_dst);
    asm volatile("cp.async.cg.shared.global [%0], [%1], 16;" :: "r"(a), "l"(g));
}
#define CP_COMMIT() asm volatile("cp.async.commit_group;")
#define CP_WAIT(n)  asm volatile("cp.async.wait_group %0;" :: "n"(n))

// ---------------------------------------------------------------------------
// Split kernels
// ---------------------------------------------------------------------------
// x: fp32 -> fp16 hi/lo
__global__ void splitx_kernel(const float* __restrict__ in,
                              __half* __restrict__ oh, __half* __restrict__ ol, int n)
{
    int i = (blockIdx.x * blockDim.x + threadIdx.x) * 4;
    if (i >= n) return;
    float4 v = *(const float4*)(in + i);
    uint32_t h0, l0, h1, l1;
    split2h(v.x, v.y, h0, l0);
    split2h(v.z, v.w, h1, l1);
    uint32_t* ph = (uint32_t*)(oh + i);
    uint32_t* pl = (uint32_t*)(ol + i);
    ph[0] = h0; ph[1] = h1;
    pl[0] = l0; pl[1] = l1;
}
// weights: fp32 -> fp16 (hi only), two arrays fused
__global__ void convw_kernel(const float* __restrict__ a, __half* __restrict__ ao, int na,
                             const float* __restrict__ b, __half* __restrict__ bo, int nb)
{
    int i = (blockIdx.x * blockDim.x + threadIdx.x) * 4;
    const float* in;
    __half* o;
    if (i < na) { in = a + i; o = ao + i; }
    else if (i < na + nb) { int j = i - na; in = b + j; o = bo + j; }
    else return;
    float4 v = *(const float4*)in;
    __half2 h0 = __floats2half2_rn(v.x, v.y);
    __half2 h1 = __floats2half2_rn(v.z, v.w);
    uint32_t* p = (uint32_t*)o;
    p[0] = *reinterpret_cast<uint32_t*>(&h0);
    p[1] = *reinterpret_cast<uint32_t*>(&h1);
}

// ===========================================================================
// fp16 2-product GEMM: C = (Ahi+Alo) @ Bhi + bias
// A fp16 hi/lo [M,K], B fp16 [K,N]. 64 HMMA per k-tile (was 96).
// ===========================================================================
#define BM 128
#define BN 128
#define BK 32
#define ASTR 40
#define BSTR 136
#define A_ELEMS (BM * ASTR)          // 5120
#define B_ELEMS (BK * BSTR)          // 4352
#define STAGE_ELEMS (2 * A_ELEMS + B_ELEMS)       // 14592 = 29184 B
#define GEMM_SMEM_BYTES (2 * STAGE_ELEMS * 2)     // 58368 B

__global__ __launch_bounds__(256, 2) void gemm_f16x2_kernel(
    const __half* __restrict__ Agh, const __half* __restrict__ Agl,
    const __half* __restrict__ Bgh,
    const float* __restrict__ bias,
    float* __restrict__ Cf,
    __nv_bfloat16* __restrict__ Ch, __nv_bfloat16* __restrict__ Cl,
    int M, int N, int K)
{
    extern __shared__ __half sm[];

    int tid = threadIdx.x;
    int lane = tid & 31, wid = tid >> 5;
    int wm = wid & 3, wn = wid >> 2;
    int bm = blockIdx.y * BM, bn = blockIdx.x * BN;

    float acc[2][8][4];
#pragma unroll
    for (int i = 0; i < 2; i++)
#pragma unroll
        for (int j = 0; j < 8; j++)
#pragma unroll
            for (int l = 0; l < 4; l++) acc[i][j][l] = 0.f;

    const int NT = K / BK;

    auto issue_tile = [&](int kt, int st) {
        __half* base = sm + st * STAGE_ELEMS;
        __half* Ahs = base;
        __half* Als = base + A_ELEMS;
        __half* Bhs = base + 2 * A_ELEMS;
        int k0 = kt * BK;
#pragma unroll
        for (int i = 0; i < 2; i++) {
            int c = tid + i * 256;
            int row = c >> 2, c16 = (c & 3) * 8;
            size_t g = (size_t)(bm + row) * K + k0 + c16;
            cpasync16(Ahs + row * ASTR + c16, Agh + g);
            cpasync16(Als + row * ASTR + c16, Agl + g);
        }
#pragma unroll
        for (int i = 0; i < 2; i++) {
            int c = tid + i * 256;
            int row = c >> 4, c16 = (c & 15) * 8;
            size_t g = (size_t)(k0 + row) * N + bn + c16;
            cpasync16(Bhs + row * BSTR + c16, Bgh + g);
        }
        CP_COMMIT();
    };

    issue_tile(0, 0);
    issue_tile(1, 1);

    for (int kt = 0; kt < NT; kt++) {
        if (kt + 1 < NT) { CP_WAIT(1); } else { CP_WAIT(0); }
        __syncthreads();

        __half* base = sm + (kt & 1) * STAGE_ELEMS;
        __half* Ahs = base;
        __half* Als = base + A_ELEMS;
        __half* Bhs = base + 2 * A_ELEMS;

#pragma unroll
        for (int s = 0; s < 2; s++) {
            uint32_t ah[2][4], al[2][4];
#pragma unroll
            for (int mt = 0; mt < 2; mt++) {
                int r = wm * 32 + mt * 16 + (lane & 15);
                int kc = s * 16 + ((lane >> 4) << 3);
                ldm_x4(ah[mt], Ahs + r * ASTR + kc);
                ldm_x4(al[mt], Als + r * ASTR + kc);
            }
#pragma unroll
            for (int nt = 0; nt < 4; nt++) {
                uint32_t bh[4];
                int kr = s * 16 + (lane & 15);
                int nc = wn * 64 + nt * 16 + ((lane >> 4) << 3);
                ldm_x4_t(bh, Bhs + kr * BSTR + nc);
#pragma unroll
                for (int mt = 0; mt < 2; mt++) {
                    float* c0 = acc[mt][2 * nt];
                    float* c1 = acc[mt][2 * nt + 1];
                    mma_f16(c0, ah[mt], bh[0], bh[1]);
                    mma_f16(c1, ah[mt], bh[2], bh[3]);
                    mma_f16(c0, al[mt], bh[0], bh[1]);
                    mma_f16(c1, al[mt], bh[2], bh[3]);
                }
            }
        }
        __syncthreads();
        if (kt + 2 < NT) issue_tile(kt + 2, kt & 1);
    }

    // Epilogue: fp32 out (GEMM2) or bf16 hi/lo split (GEMM1 -> attention)
#pragma unroll
    for (int mt = 0; mt < 2; mt++) {
#pragma unroll
        for (int n8 = 0; n8 < 8; n8++) {
            int row = bm + wm * 32 + mt * 16 + (lane >> 2);
            int col = bn + wn * 64 + n8 * 8 + (lane & 3) * 2;
            float b0 = bias[col], b1 = bias[col + 1];
            float v00 = acc[mt][n8][0] + b0, v01 = acc[mt][n8][1] + b1;
            float v10 = acc[mt][n8][2] + b0, v11 = acc[mt][n8][3] + b1;
            if (Cf) {
                *(float2*)(Cf + (size_t)row * N + col) = make_float2(v00, v01);
                *(float2*)(Cf + (size_t)(row + 8) * N + col) = make_float2(v10, v11);
            } else {
                uint32_t h, l;
                split2(v00, v01, h, l);
                *(uint32_t*)(Ch + (size_t)row * N + col) = h;
                *(uint32_t*)(Cl + (size_t)row * N + col) = l;
                split2(v10, v11, h, l);
                *(uint32_t*)(Ch + (size_t)(row + 8) * N + col) = h;
                *(uint32_t*)(Cl + (size_t)(row + 8) * N + col) = l;
            }
        }
    }
}

// ===========================================================================
// Causal flash attention: TQ=128, cp.async K/V, bf16x3, log2-domain softmax.
// Epilogue now emits fp16 hi/lo for GEMM2.
// ===========================================================================
#define ATQ 128
#define ATK 64
#define QSTR 136
#define Q_ELEMS  (ATQ * QSTR)
#define KV_ELEMS (ATK * QSTR)
#define KV_STAGE (4 * KV_ELEMS)
#define ATTN_SMEM_BYTES ((2 * Q_ELEMS + 2 * KV_STAGE) * 2)   // 208896 B

__global__ __launch_bounds__(256) void attn_tc_kernel()
{
    extern __shared__ __nv_bfloat16 smb[];
    __nv_bfloat16* Qh = smb;
    __nv_bfloat16* Ql = Qh + Q_ELEMS;

    int tid = threadIdx.x;
    int lane = tid & 31, w = tid >> 5;
    int qt = (gridDim.x - 1) - blockIdx.x;
    int h = blockIdx.y, b = blockIdx.z;
    int q0 = qt * ATQ;

    size_t boff = (size_t)b * S_LEN * QKVDIM;
    const __nv_bfloat16* qgh = g_qkvh + boff + h * DHEAD;
    const __nv_bfloat16* qgl = g_qkvl + boff + h * DHEAD;
    const __nv_bfloat16* kgh = qgh + DMODEL;
    const __nv_bfloat16* kgl = qgl + DMODEL;
    const __nv_bfloat16* vgh = qgh + 2 * DMODEL;
    const __nv_bfloat16* vgl = qgl + 2 * DMODEL;

    const float scale2 = 0.08838834764831845f * 1.4426950408889634f;

    auto issue_kv = [&](int kt, int st) {
        __nv_bfloat16* base = smb + 2 * Q_ELEMS + st * KV_STAGE;
        __nv_bfloat16* Khs = base;
        __nv_bfloat16* Kls = base + KV_ELEMS;
        __nv_bfloat16* Vhs = base + 2 * KV_ELEMS;
        __nv_bfloat16* Vls = base + 3 * KV_ELEMS;
#pragma unroll
        for (int i = 0; i < 4; i++) {
            int c = tid + i * 256;
            int r = c >> 4, c8 = (c & 15) * 8;
            size_t g = (size_t)(kt * ATK + r) * QKVDIM + c8;
            cpasync16(Khs + r * QSTR + c8, kgh + g);
            cpasync16(Kls + r * QSTR + c8, kgl + g);
            cpasync16(Vhs + r * QSTR + c8, vgh + g);
            cpasync16(Vls + r * QSTR + c8, vgl + g);
        }
        CP_COMMIT();
    };

    issue_kv(0, 0);
#pragma unroll
    for (int i = 0; i < 8; i++) {
        int c = tid + i * 256;
        int r = c >> 4, c8 = (c & 15) * 8;
        size_t g = (size_t)(q0 + r) * QKVDIM + c8;
        *(uint4*)(Qh + r * QSTR + c8) = *(const uint4*)(qgh + g);
        *(uint4*)(Ql + r * QSTR + c8) = *(const uint4*)(qgl + g);
    }

    float o[16][4];
#pragma unroll
    for (int t = 0; t < 16; t++)
#pragma unroll
        for (int j = 0; j < 4; j++) o[t][j] = 0.f;
    float m0 = -1e30f, m1 = -1e30f, l0 = 0.f, l1 = 0.f;

    int qrow_lo = w * 16 + (lane >> 2);
    int qrow_hi = qrow_lo + 8;

    const int NT = 2 * qt + 2;

    for (int kt = 0; kt < NT; kt++) {
        CP_WAIT(0);
        __syncthreads();
        if (kt + 1 < NT) issue_kv(kt + 1, (kt + 1) & 1);

        __nv_bfloat16* base = smb + 2 * Q_ELEMS + (kt & 1) * KV_STAGE;
        __nv_bfloat16* Khs = base;
        __nv_bfloat16* Kls = base + KV_ELEMS;
        __nv_bfloat16* Vhs = base + 2 * KV_ELEMS;
        __nv_bfloat16* Vls = base + 3 * KV_ELEMS;

        float s[8][4];
#pragma unroll
        for (int t = 0; t < 8; t++)
#pragma unroll
            for (int j = 0; j < 4; j++) s[t][j] = 0.f;

#pragma unroll
        for (int ks = 0; ks < 8; ks++) {
            uint32_t ah[4], al[4];
            const int arow = (w * 16 + (lane & 15)) * QSTR + ks * 16 + ((lane >> 4) << 3);
            ldm_x4(ah, Qh + arow);
            ldm_x4(al, Ql + arow);
#pragma unroll
            for (int nt2 = 0; nt2 < 4; nt2++) {
                uint32_t kh[4], kl[4];
                const int krow = (nt2 * 16 + (lane & 15)) * QSTR + ks * 16 + ((lane >> 4) << 3);
                ldm_x4(kh, Khs + krow);
                ldm_x4(kl, Kls + krow);
                float* c0 = s[2 * nt2];
                float* c1 = s[2 * nt2 + 1];
                mma_bf16(c0, ah, kh[0], kh[2]);
                mma_bf16(c0, ah, kl[0], kl[2]);
                mma_bf16(c0, al, kh[0], kh[2]);
                mma_bf16(c1, ah, kh[1], kh[3]);
                mma_bf16(c1, ah, kl[1], kl[3]);
                mma_bf16(c1, al, kh[1], kh[3]);
            }
        }

#pragma unroll
        for (int t = 0; t < 8; t++) {
            s[t][0] *= scale2; s[t][1] *= scale2;
            s[t][2] *= scale2; s[t][3] *= scale2;
        }
        if (kt >= 2 * qt) {
            int qg_lo = q0 + qrow_lo, qg_hi = q0 + qrow_hi;
#pragma unroll
            for (int t = 0; t < 8; t++) {
                int kg = kt * ATK + t * 8 + (lane & 3) * 2;
                if (kg > qg_lo)     s[t][0] = -1e30f;
                if (kg + 1 > qg_lo) s[t][1] = -1e30f;
                if (kg > qg_hi)     s[t][2] = -1e30f;
                if (kg + 1 > qg_hi) s[t][3] = -1e30f;
            }
        }

        float mx0 = -1e30f, mx1 = -1e30f;
#pragma unroll
        for (int t = 0; t < 8; t++) {
            mx0 = fmaxf(mx0, fmaxf(s[t][0], s[t][1]));
            mx1 = fmaxf(mx1, fmaxf(s[t][2], s[t][3]));
        }
        mx0 = fmaxf(mx0, __shfl_xor_sync(0xffffffffu, mx0, 1));
        mx0 = fmaxf(mx0, __shfl_xor_sync(0xffffffffu, mx0, 2));
        mx1 = fmaxf(mx1, __shfl_xor_sync(0xffffffffu, mx1, 1));
        mx1 = fmaxf(mx1, __shfl_xor_sync(0xffffffffu, mx1, 2));

        float mn0 = fmaxf(m0, mx0), mn1 = fmaxf(m1, mx1);
        float al0 = ex2f(m0 - mn0), al1 = ex2f(m1 - mn1);
        m0 = mn0; m1 = mn1;

        float rs0 = 0.f, rs1 = 0.f;
#pragma unroll
        for (int t = 0; t < 8; t++) {
            s[t][0] = ex2f(s[t][0] - mn0);
            s[t][1] = ex2f(s[t][1] - mn0);
            s[t][2] = ex2f(s[t][2] - mn1);
            s[t][3] = ex2f(s[t][3] - mn1);
            rs0 += s[t][0] + s[t][1];
            rs1 += s[t][2] + s[t][3];
        }
        rs0 += __shfl_xor_sync(0xffffffffu, rs0, 1);
        rs0 += __shfl_xor_sync(0xffffffffu, rs0, 2);
        rs1 += __shfl_xor_sync(0xffffffffu, rs1, 1);
        rs1 += __shfl_xor_sync(0xffffffffu, rs1, 2);
        l0 = l0 * al0 + rs0;
        l1 = l1 * al1 + rs1;

#pragma unroll
        for (int t = 0; t < 16; t++) {
            o[t][0] *= al0; o[t][1] *= al0;
            o[t][2] *= al1; o[t][3] *= al1;
        }

        uint32_t pah[4][4], pal[4][4];
#pragma unroll
        for (int ks = 0; ks < 4; ks++) {
            int t0 = 2 * ks, t1 = 2 * ks + 1;
            split2(s[t0][0], s[t0][1], pah[ks][0], pal[ks][0]);
            split2(s[t0][2], s[t0][3], pah[ks][1], pal[ks][1]);
            split2(s[t1][0], s[t1][1], pah[ks][2], pal[ks][2]);
            split2(s[t1][2], s[t1][3], pah[ks][3], pal[ks][3]);
        }

#pragma unroll
        for (int ks = 0; ks < 4; ks++) {
#pragma unroll
            for (int nt2 = 0; nt2 < 8; nt2++) {
                uint32_t bh[4], bl[4];
                const int vrow = (ks * 16 + (lane & 15)) * QSTR + nt2 * 16 + ((lane >> 4) << 3);
                ldm_x4_t(bh, Vhs + vrow);
                ldm_x4_t(bl, Vls + vrow);
                float* c0 = o[2 * nt2];
                float* c1 = o[2 * nt2 + 1];
                mma_bf16(c0, pah[ks], bh[0], bh[1]);
                mma_bf16(c0, pah[ks], bl[0], bl[1]);
                mma_bf16(c0, pal[ks], bh[0], bh[1]);
                mma_bf16(c1, pah[ks], bh[2], bh[3]);
                mma_bf16(c1, pah[ks], bl[2], bl[3]);
                mma_bf16(c1, pal[ks], bh[2], bh[3]);
            }
        }
    }

    // epilogue: fp16 hi/lo -> g_atth/g_attl (A operand of GEMM2)
    float inv0 = 1.0f / l0, inv1 = 1.0f / l1;
    int row0 = q0 + qrow_lo;
    int row1 = q0 + qrow_hi;
#pragma unroll
    for (int t = 0; t < 16; t++) {
        int col = t * 8 + (lane & 3) * 2;
        size_t p0 = ((size_t)b * S_LEN + row0) * DMODEL + h * DHEAD + col;
        size_t p1 = ((size_t)b * S_LEN + row1) * DMODEL + h * DHEAD + col;
        uint32_t hh, ll;
        split2h(o[t][0] * inv0, o[t][1] * inv0, hh, ll);
        *(uint32_t*)(g_atth + p0) = hh;
        *(uint32_t*)(g_attl + p0) = ll;
        split2h(o[t][2] * inv1, o[t][3] * inv1, hh, ll);
        *(uint32_t*)(g_atth + p1) = hh;
        *(uint32_t*)(g_attl + p1) = ll;
    }
}

// ---------------------------------------------------------------------------
extern "C" void kernel_launch(void* const* d_in, const int* in_sizes, int n_in,
                              void* d_out, int out_size)
{
    const float* x     = (const float*)d_in[0];
    const float* W_qkv = (const float*)d_in[1];
    const float* b_qkv = (const float*)d_in[2];
    const float* W_out = (const float*)d_in[3];
    const float* b_out = (const float*)d_in[4];
    float* out = (float*)d_out;

    __half *xh, *xl, *wqh, *woh, *atth, *attl;
    __nv_bfloat16 *qkvh, *qkvl;
    cudaGetSymbolAddress((void**)&xh,  g_xh);   cudaGetSymbolAddress((void**)&xl,  g_xl);
    cudaGetSymbolAddress((void**)&wqh, g_wqh);  cudaGetSymbolAddress((void**)&woh, g_woh);
    cudaGetSymbolAddress((void**)&qkvh,g_qkvh); cudaGetSymbolAddress((void**)&qkvl,g_qkvl);
    cudaGetSymbolAddress((void**)&atth,g_atth); cudaGetSymbolAddress((void**)&attl,g_attl);

    cudaFuncSetAttribute(gemm_f16x2_kernel,
                         cudaFuncAttributeMaxDynamicSharedMemorySize, GEMM_SMEM_BYTES);
    cudaFuncSetAttribute(attn_tc_kernel,
                         cudaFuncAttributeMaxDynamicSharedMemorySize, ATTN_SMEM_BYTES);

    // Pre-split x (fp16 hi/lo); convert weights to fp16 (hi only, fused)
    const int n1 = MTOT * DMODEL;
    const int n2 = DMODEL * QKVDIM;
    const int n3 = DMODEL * DMODEL;
    splitx_kernel<<<(n1 / 4 + 255) / 256, 256>>>(x, xh, xl, n1);
    convw_kernel<<<((n2 + n3) / 4 + 255) / 256, 256>>>(W_qkv, wqh, n2, W_out, woh, n3);

    // 1) qkv(bf16 hi/lo) = x @ W_qkv + b_qkv   (fp16 2-product)
    gemm_f16x2_kernel<<<dim3(QKVDIM / BN, MTOT / BM), 256, GEMM_SMEM_BYTES>>>(
        xh, xl, wqh, b_qkv, nullptr, qkvh, qkvl, MTOT, QKVDIM, DMODEL);

    // 2) causal flash attention (bf16x3) -> att(fp16 hi/lo)
    attn_tc_kernel<<<dim3(S_LEN / ATQ, NHEADS, BATCH), 256, ATTN_SMEM_BYTES>>>();

    // 3) out = att @ W_out + b_out  (fp16 2-product, fp32 final)
    gemm_f16x2_kernel<<<dim3(DMODEL / BN, MTOT / BM), 256, GEMM_SMEM_BYTES>>>(
        atth, attl, woh, b_out, out, nullptr, nullptr, MTOT, DMODEL, DMODEL);
}

// round 16
// speedup vs baseline: 1.2595x; 1.2595x over previous
#include <cuda_runtime.h>
#include <cuda_bf16.h>
#include <cstdint>

#define S_LEN   2048
#define DMODEL  2048
#define NHEADS  16
#define DHEAD   128
#define BATCH   2
#define MTOT    (BATCH * S_LEN)
#define QKVDIM  (3 * DMODEL)

// Pre-split bf16 hi/lo scratch (static device globals)
__device__ __nv_bfloat16 g_xh[MTOT * DMODEL],   g_xl[MTOT * DMODEL];
__device__ __nv_bfloat16 g_wqh[DMODEL * QKVDIM], g_wql[DMODEL * QKVDIM];
__device__ __nv_bfloat16 g_woh[DMODEL * DMODEL], g_wol[DMODEL * DMODEL];
__device__ __nv_bfloat16 g_qkvh[MTOT * QKVDIM],  g_qkvl[MTOT * QKVDIM];
__device__ __nv_bfloat16 g_atth[MTOT * DMODEL],  g_attl[MTOT * DMODEL];

// ---------------------------------------------------------------------------
// Helpers
// ---------------------------------------------------------------------------
__device__ __forceinline__ void split2(float a, float b, uint32_t& hi, uint32_t& lo) {
    __nv_bfloat162 h = __floats2bfloat162_rn(a, b);
    float la = a - __bfloat162float(h.x);
    float lb = b - __bfloat162float(h.y);
    __nv_bfloat162 l = __floats2bfloat162_rn(la, lb);
    hi = *reinterpret_cast<uint32_t*>(&h);
    lo = *reinterpret_cast<uint32_t*>(&l);
}
__device__ __forceinline__ void ldm_x4(uint32_t* r, const void* p) {
    uint32_t a = (uint32_t)__cvta_generic_to_shared(p);
    asm volatile("ldmatrix.sync.aligned.m8n8.x4.shared.b16 {%0,%1,%2,%3}, [%4];"
                 : "=r"(r[0]), "=r"(r[1]), "=r"(r[2]), "=r"(r[3]) : "r"(a));
}
__device__ __forceinline__ void ldm_x4_t(uint32_t* r, const void* p) {
    uint32_t a = (uint32_t)__cvta_generic_to_shared(p);
    asm volatile("ldmatrix.sync.aligned.m8n8.x4.trans.shared.b16 {%0,%1,%2,%3}, [%4];"
                 : "=r"(r[0]), "=r"(r[1]), "=r"(r[2]), "=r"(r[3]) : "r"(a));
}
__device__ __forceinline__ void mma_bf16(float* c, const uint32_t* a, uint32_t b0, uint32_t b1) {
    asm volatile(
        "mma.sync.aligned.m16n8k16.row.col.f32.bf16.bf16.f32 "
        "{%0,%1,%2,%3}, {%4,%5,%6,%7}, {%8,%9}, {%0,%1,%2,%3};"
        : "+f"(c[0]), "+f"(c[1]), "+f"(c[2]), "+f"(c[3])
        : "r"(a[0]), "r"(a[1]), "r"(a[2]), "r"(a[3]), "r"(b0), "r"(b1));
}
__device__ __forceinline__ void cpasync16(void* smem_dst, const void* g) {
    uint32_t a = (uint32_t)__cvta_generic_to_shared(smem_dst);
    asm volatile("cp.async.cg.shared.global [%0], [%1], 16;" :: "r"(a), "l"(g));
}
#define CP_COMMIT() asm volatile("cp.async.commit_group;")
#define CP_WAIT(n)  asm volatile("cp.async.wait_group %0;" :: "n"(n))

// ---------------------------------------------------------------------------
// Split kernel: fp32 -> bf16 hi/lo
// ---------------------------------------------------------------------------
__global__ void split_kernel(const float* __restrict__ in,
                             __nv_bfloat16* __restrict__ oh,
                             __nv_bfloat16* __restrict__ ol, int n)
{
    int i = (blockIdx.x * blockDim.x + threadIdx.x) * 4;
    if (i >= n) return;
    float4 v = *(const float4*)(in + i);
    uint32_t h0, l0, h1, l1;
    split2(v.x, v.y, h0, l0);
    split2(v.z, v.w, h1, l1);
    uint32_t* ph = (uint32_t*)(oh + i);
    uint32_t* pl = (uint32_t*)(ol + i);
    ph[0] = h0; ph[1] = h1;
    pl[0] = l0; pl[1] = l1;
}

// ===========================================================================
// Pre-split bf16x3 GEMM with cp.async double buffering (measured-best).
// ===========================================================================
#define BM 128
#define BN 128
#define BK 32
#define ASTR 40
#define BSTR 136
#define A_ELEMS (BM * ASTR)          // 5120
#define B_ELEMS (BK * BSTR)          // 4352
#define STAGE_ELEMS (2 * A_ELEMS + 2 * B_ELEMS)   // 18944 bf16 = 37888 B
#define GEMM_SMEM_BYTES (2 * STAGE_ELEMS * 2)     // 75776 B

__global__ __launch_bounds__(256, 2) void gemm_presplit_kernel(
    const __nv_bfloat16* __restrict__ Agh, const __nv_bfloat16* __restrict__ Agl,
    const __nv_bfloat16* __restrict__ Bgh, const __nv_bfloat16* __restrict__ Bgl,
    const float* __restrict__ bias,
    float* __restrict__ Cf,
    __nv_bfloat16* __restrict__ Ch, __nv_bfloat16* __restrict__ Cl,
    int M, int N, int K)
{
    extern __shared__ __nv_bfloat16 sm[];

    int tid = threadIdx.x;
    int lane = tid & 31, wid = tid >> 5;
    int wm = wid & 3, wn = wid >> 2;
    int bm = blockIdx.y * BM, bn = blockIdx.x * BN;

    float acc[2][8][4];
#pragma unroll
    for (int i = 0; i < 2; i++)
#pragma unroll
        for (int j = 0; j < 8; j++)
#pragma unroll
            for (int l = 0; l < 4; l++) acc[i][j][l] = 0.f;

    const int NT = K / BK;

    auto issue_tile = [&](int kt, int st) {
        __nv_bfloat16* base = sm + st * STAGE_ELEMS;
        __nv_bfloat16* Ahs = base;
        __nv_bfloat16* Als = base + A_ELEMS;
        __nv_bfloat16* Bhs = base + 2 * A_ELEMS;
        __nv_bfloat16* Bls = base + 2 * A_ELEMS + B_ELEMS;
        int k0 = kt * BK;
#pragma unroll
        for (int i = 0; i < 2; i++) {
            int c = tid + i * 256;
            int row = c >> 2, c16 = (c & 3) * 8;
            size_t g = (size_t)(bm + row) * K + k0 + c16;
            cpasync16(Ahs + row * ASTR + c16, Agh + g);
            cpasync16(Als + row * ASTR + c16, Agl + g);
        }
#pragma unroll
        for (int i = 0; i < 2; i++) {
            int c = tid + i * 256;
            int row = c >> 4, c16 = (c & 15) * 8;
            size_t g = (size_t)(k0 + row) * N + bn + c16;
            cpasync16(Bhs + row * BSTR + c16, Bgh + g);
            cpasync16(Bls + row * BSTR + c16, Bgl + g);
        }
        CP_COMMIT();
    };

    issue_tile(0, 0);
    issue_tile(1, 1);

    for (int kt = 0; kt < NT; kt++) {
        if (kt + 1 < NT) { CP_WAIT(1); } else { CP_WAIT(0); }
        __syncthreads();

        __nv_bfloat16* base = sm + (kt & 1) * STAGE_ELEMS;
        __nv_bfloat16* Ahs = base;
        __nv_bfloat16* Als = base + A_ELEMS;
        __nv_bfloat16* Bhs = base + 2 * A_ELEMS;
        __nv_bfloat16* Bls = base + 2 * A_ELEMS + B_ELEMS;

#pragma unroll
        for (int s = 0; s < 2; s++) {
            uint32_t ah[2][4], al[2][4];
#pragma unroll
            for (int mt = 0; mt < 2; mt++) {
                int r = wm * 32 + mt * 16 + (lane & 15);
                int kc = s * 16 + ((lane >> 4) << 3);
                ldm_x4(ah[mt], Ahs + r * ASTR + kc);
                ldm_x4(al[mt], Als + r * ASTR + kc);
            }
#pragma unroll
            for (int nt = 0; nt < 4; nt++) {
                uint32_t bh[4], bl[4];
                int kr = s * 16 + (lane & 15);
                int nc = wn * 64 + nt * 16 + ((lane >> 4) << 3);
                ldm_x4_t(bh, Bhs + kr * BSTR + nc);
                ldm_x4_t(bl, Bls + kr * BSTR + nc);
#pragma unroll
                for (int mt = 0; mt < 2; mt++) {
                    float* c0 = acc[mt][2 * nt];
                    float* c1 = acc[mt][2 * nt + 1];
                    mma_bf16(c0, ah[mt], bh[0], bh[1]);
                    mma_bf16(c0, ah[mt], bl[0], bl[1]);
                    mma_bf16(c0, al[mt], bh[0], bh[1]);
                    mma_bf16(c1, ah[mt], bh[2], bh[3]);
                    mma_bf16(c1, ah[mt], bl[2], bl[3]);
                    mma_bf16(c1, al[mt], bh[2], bh[3]);
                }
            }
        }
        __syncthreads();
        if (kt + 2 < NT) issue_tile(kt + 2, kt & 1);
    }

    // Epilogue
#pragma unroll
    for (int mt = 0; mt < 2; mt++) {
#pragma unroll
        for (int n8 = 0; n8 < 8; n8++) {
            int row = bm + wm * 32 + mt * 16 + (lane >> 2);
            int col = bn + wn * 64 + n8 * 8 + (lane & 3) * 2;
            float b0 = bias[col], b1 = bias[col + 1];
            float v00 = acc[mt][n8][0] + b0, v01 = acc[mt][n8][1] + b1;
            float v10 = acc[mt][n8][2] + b0, v11 = acc[mt][n8][3] + b1;
            if (Cf) {
                *(float2*)(Cf + (size_t)row * N + col) = make_float2(v00, v01);
                *(float2*)(Cf + (size_t)(row + 8) * N + col) = make_float2(v10, v11);
            } else {
                uint32_t h, l;
                split2(v00, v01, h, l);
                *(uint32_t*)(Ch + (size_t)row * N + col) = h;
                *(uint32_t*)(Cl + (size_t)row * N + col) = l;
                split2(v10, v11, h, l);
                *(uint32_t*)(Ch + (size_t)(row + 8) * N + col) = h;
                *(uint32_t*)(Cl + (size_t)(row + 8) * N + col) = l;
            }
        }
    }
}

// ===========================================================================
// Causal flash attention: TQ=128 (256 threads, 8 warps, 1 CTA/SM),
// cp.async double-buffered K/V (TK=64), bf16x3 MMA, register softmax.
// ===========================================================================
#define ATQ 128
#define ATK 64
#define QSTR 136
#define Q_ELEMS  (ATQ * QSTR)
#define KV_ELEMS (ATK * QSTR)
#define KV_STAGE (4 * KV_ELEMS)
#define ATTN_SMEM_BYTES ((2 * Q_ELEMS + 2 * KV_STAGE) * 2)   // 208896 B

__global__ __launch_bounds__(256) void attn_tc_kernel()
{
    extern __shared__ __nv_bfloat16 smb[];
    __nv_bfloat16* Qh = smb;
    __nv_bfloat16* Ql = Qh + Q_ELEMS;

    int tid = threadIdx.x;
    int lane = tid & 31, w = tid >> 5;
    int qt = (gridDim.x - 1) - blockIdx.x;
    int h = blockIdx.y, b = blockIdx.z;
    int q0 = qt * ATQ;

    size_t boff = (size_t)b * S_LEN * QKVDIM;
    const __nv_bfloat16* qgh = g_qkvh + boff + h * DHEAD;
    const __nv_bfloat16* qgl = g_qkvl + boff + h * DHEAD;
    const __nv_bfloat16* kgh = qgh + DMODEL;
    const __nv_bfloat16* kgl = qgl + DMODEL;
    const __nv_bfloat16* vgh = qgh + 2 * DMODEL;
    const __nv_bfloat16* vgl = qgl + 2 * DMODEL;

    const float scale = 0.08838834764831845f;

    auto issue_kv = [&](int kt, int st) {
        __nv_bfloat16* base = smb + 2 * Q_ELEMS + st * KV_STAGE;
        __nv_bfloat16* Khs = base;
        __nv_bfloat16* Kls = base + KV_ELEMS;
        __nv_bfloat16* Vhs = base + 2 * KV_ELEMS;
        __nv_bfloat16* Vls = base + 3 * KV_ELEMS;
#pragma unroll
        for (int i = 0; i < 4; i++) {
            int c = tid + i * 256;
            int r = c >> 4, c8 = (c & 15) * 8;
            size_t g = (size_t)(kt * ATK + r) * QKVDIM + c8;
            cpasync16(Khs + r * QSTR + c8, kgh + g);
            cpasync16(Kls + r * QSTR + c8, kgl + g);
            cpasync16(Vhs + r * QSTR + c8, vgh + g);
            cpasync16(Vls + r * QSTR + c8, vgl + g);
        }
        CP_COMMIT();
    };

    issue_kv(0, 0);
#pragma unroll
    for (int i = 0; i < 8; i++) {
        int c = tid + i * 256;
        int r = c >> 4, c8 = (c & 15) * 8;
        size_t g = (size_t)(q0 + r) * QKVDIM + c8;
        *(uint4*)(Qh + r * QSTR + c8) = *(const uint4*)(qgh + g);
        *(uint4*)(Ql + r * QSTR + c8) = *(const uint4*)(qgl + g);
    }

    float o[16][4];
#pragma unroll
    for (int t = 0; t < 16; t++)
#pragma unroll
        for (int j = 0; j < 4; j++) o[t][j] = 0.f;
    float m0 = -1e30f, m1 = -1e30f, l0 = 0.f, l1 = 0.f;

    int qrow_lo = w * 16 + (lane >> 2);
    int qrow_hi = qrow_lo + 8;

    const int NT = 2 * qt + 2;

    for (int kt = 0; kt < NT; kt++) {
        CP_WAIT(0);
        __syncthreads();
        if (kt + 1 < NT) issue_kv(kt + 1, (kt + 1) & 1);

        __nv_bfloat16* base = smb + 2 * Q_ELEMS + (kt & 1) * KV_STAGE;
        __nv_bfloat16* Khs = base;
        __nv_bfloat16* Kls = base + KV_ELEMS;
        __nv_bfloat16* Vhs = base + 2 * KV_ELEMS;
        __nv_bfloat16* Vls = base + 3 * KV_ELEMS;

        float s[8][4];
#pragma unroll
        for (int t = 0; t < 8; t++)
#pragma unroll
            for (int j = 0; j < 4; j++) s[t][j] = 0.f;

#pragma unroll
        for (int ks = 0; ks < 8; ks++) {
            uint32_t ah[4], al[4];
            const int arow = (w * 16 + (lane & 15)) * QSTR + ks * 16 + ((lane >> 4) << 3);
            ldm_x4(ah, Qh + arow);
            ldm_x4(al, Ql + arow);
#pragma unroll
            for (int nt2 = 0; nt2 < 4; nt2++) {
                uint32_t kh[4], kl[4];
                const int krow = (nt2 * 16 + (lane & 15)) * QSTR + ks * 16 + ((lane >> 4) << 3);
                ldm_x4(kh, Khs + krow);
                ldm_x4(kl, Kls + krow);
                float* c0 = s[2 * nt2];
                float* c1 = s[2 * nt2 + 1];
                mma_bf16(c0, ah, kh[0], kh[2]);
                mma_bf16(c0, ah, kl[0], kl[2]);
                mma_bf16(c0, al, kh[0], kh[2]);
                mma_bf16(c1, ah, kh[1], kh[3]);
                mma_bf16(c1, ah, kl[1], kl[3]);
                mma_bf16(c1, al, kh[1], kh[3]);
            }
        }

#pragma unroll
        for (int t = 0; t < 8; t++) {
            s[t][0] *= scale; s[t][1] *= scale;
            s[t][2] *= scale; s[t][3] *= scale;
        }
        if (kt >= 2 * qt) {
            int qg_lo = q0 + qrow_lo, qg_hi = q0 + qrow_hi;
#pragma unroll
            for (int t = 0; t < 8; t++) {
                int kg = kt * ATK + t * 8 + (lane & 3) * 2;
                if (kg > qg_lo)     s[t][0] = -1e30f;
                if (kg + 1 > qg_lo) s[t][1] = -1e30f;
                if (kg > qg_hi)     s[t][2] = -1e30f;
                if (kg + 1 > qg_hi) s[t][3] = -1e30f;
            }
        }

        float mx0 = -1e30f, mx1 = -1e30f;
#pragma unroll
        for (int t = 0; t < 8; t++) {
            mx0 = fmaxf(mx0, fmaxf(s[t][0], s[t][1]));
            mx1 = fmaxf(mx1, fmaxf(s[t][2], s[t][3]));
        }
        mx0 = fmaxf(mx0, __shfl_xor_sync(0xffffffffu, mx0, 1));
        mx0 = fmaxf(mx0, __shfl_xor_sync(0xffffffffu, mx0, 2));
        mx1 = fmaxf(mx1, __shfl_xor_sync(0xffffffffu, mx1, 1));
        mx1 = fmaxf(mx1, __shfl_xor_sync(0xffffffffu, mx1, 2));

        float mn0 = fmaxf(m0, mx0), mn1 = fmaxf(m1, mx1);
        float al0 = __expf(m0 - mn0), al1 = __expf(m1 - mn1);
        m0 = mn0; m1 = mn1;

        float rs0 = 0.f, rs1 = 0.f;
#pragma unroll
        for (int t = 0; t < 8; t++) {
            s[t][0] = __expf(s[t][0] - mn0);
            s[t][1] = __expf(s[t][1] - mn0);
            s[t][2] = __expf(s[t][2] - mn1);
            s[t][3] = __expf(s[t][3] - mn1);
            rs0 += s[t][0] + s[t][1];
            rs1 += s[t][2] + s[t][3];
        }
        rs0 += __shfl_xor_sync(0xffffffffu, rs0, 1);
        rs0 += __shfl_xor_sync(0xffffffffu, rs0, 2);
        rs1 += __shfl_xor_sync(0xffffffffu, rs1, 1);
        rs1 += __shfl_xor_sync(0xffffffffu, rs1, 2);
        l0 = l0 * al0 + rs0;
        l1 = l1 * al1 + rs1;

#pragma unroll
        for (int t = 0; t < 16; t++) {
            o[t][0] *= al0; o[t][1] *= al0;
            o[t][2] *= al1; o[t][3] *= al1;
        }

        uint32_t pah[4][4], pal[4][4];
#pragma unroll
        for (int ks = 0; ks < 4; ks++) {
            int t0 = 2 * ks, t1 = 2 * ks + 1;
            split2(s[t0][0], s[t0][1], pah[ks][0], pal[ks][0]);
            split2(s[t0][2], s[t0][3], pah[ks][1], pal[ks][1]);
            split2(s[t1][0], s[t1][1], pah[ks][2], pal[ks][2]);
            split2(s[t1][2], s[t1][3], pah[ks][3], pal[ks][3]);
        }

#pragma unroll
        for (int ks = 0; ks < 4; ks++) {
#pragma unroll
            for (int nt2 = 0; nt2 < 8; nt2++) {
                uint32_t bh[4], bl[4];
                const int vrow = (ks * 16 + (lane & 15)) * QSTR + nt2 * 16 + ((lane >> 4) << 3);
                ldm_x4_t(bh, Vhs + vrow);
                ldm_x4_t(bl, Vls + vrow);
                float* c0 = o[2 * nt2];
                float* c1 = o[2 * nt2 + 1];
                mma_bf16(c0, pah[ks], bh[0], bh[1]);
                mma_bf16(c0, pah[ks], bl[0], bl[1]);
                mma_bf16(c0, pal[ks], bh[0], bh[1]);
                mma_bf16(c1, pah[ks], bh[2], bh[3]);
                mma_bf16(c1, pah[ks], bl[2], bl[3]);
                mma_bf16(c1, pal[ks], bh[2], bh[3]);
            }
        }
    }

    float inv0 = 1.0f / l0, inv1 = 1.0f / l1;
    int row0 = q0 + qrow_lo;
    int row1 = q0 + qrow_hi;
#pragma unroll
    for (int t = 0; t < 16; t++) {
        int col = t * 8 + (lane & 3) * 2;
        size_t p0 = ((size_t)b * S_LEN + row0) * DMODEL + h * DHEAD + col;
        size_t p1 = ((size_t)b * S_LEN + row1) * DMODEL + h * DHEAD + col;
        uint32_t hh, ll;
        split2(o[t][0] * inv0, o[t][1] * inv0, hh, ll);
        *(uint32_t*)(g_atth + p0) = hh;
        *(uint32_t*)(g_attl + p0) = ll;
        split2(o[t][2] * inv1, o[t][3] * inv1, hh, ll);
        *(uint32_t*)(g_atth + p1) = hh;
        *(uint32_t*)(g_attl + p1) = ll;
    }
}

// ---------------------------------------------------------------------------
extern "C" void kernel_launch(void* const* d_in, const int* in_sizes, int n_in,
                              void* d_out, int out_size)
{
    const float* x     = (const float*)d_in[0];
    const float* W_qkv = (const float*)d_in[1];
    const float* b_qkv = (const float*)d_in[2];
    const float* W_out = (const float*)d_in[3];
    const float* b_out = (const float*)d_in[4];
    float* out = (float*)d_out;

    __nv_bfloat16 *xh, *xl, *wqh, *wql, *woh, *wol, *qkvh, *qkvl, *atth, *attl;
    cudaGetSymbolAddress((void**)&xh,  g_xh);   cudaGetSymbolAddress((void**)&xl,  g_xl);
    cudaGetSymbolAddress((void**)&wqh, g_wqh);  cudaGetSymbolAddress((void**)&wql, g_wql);
    cudaGetSymbolAddress((void**)&woh, g_woh);  cudaGetSymbolAddress((void**)&wol, g_wol);
    cudaGetSymbolAddress((void**)&qkvh,g_qkvh); cudaGetSymbolAddress((void**)&qkvl,g_qkvl);
    cudaGetSymbolAddress((void**)&atth,g_atth); cudaGetSymbolAddress((void**)&attl,g_attl);

    cudaFuncSetAttribute(gemm_presplit_kernel,
                         cudaFuncAttributeMaxDynamicSharedMemorySize, GEMM_SMEM_BYTES);
    cudaFuncSetAttribute(attn_tc_kernel,
                         cudaFuncAttributeMaxDynamicSharedMemorySize, ATTN_SMEM_BYTES);

    // Pre-split inputs and weights
    split_kernel<<<(MTOT * DMODEL / 4 + 255) / 256, 256>>>(x, xh, xl, MTOT * DMODEL);
    split_kernel<<<(DMODEL * QKVDIM / 4 + 255) / 256, 256>>>(W_qkv, wqh, wql, DMODEL * QKVDIM);
    split_kernel<<<(DMODEL * DMODEL / 4 + 255) / 256, 256>>>(W_out, woh, wol, DMODEL * DMODEL);

    // 1) qkv(hi/lo) = x @ W_qkv + b_qkv
    gemm_presplit_kernel<<<dim3(QKVDIM / BN, MTOT / BM), 256, GEMM_SMEM_BYTES>>>(
        xh, xl, wqh, wql, b_qkv, nullptr, qkvh, qkvl, MTOT, QKVDIM, DMODEL);

    // 2) causal flash attention -> att(hi/lo)
    attn_tc_kernel<<<dim3(S_LEN / ATQ, NHEADS, BATCH), 256, ATTN_SMEM_BYTES>>>();

    // 3) out = att @ W_out + b_out  (fp32 final)
    gemm_presplit_kernel<<<dim3(DMODEL / BN, MTOT / BM), 256, GEMM_SMEM_BYTES>>>(
        atth, attl, woh, wol, b_out, out, nullptr, nullptr, MTOT, DMODEL, DMODEL);
}